// round 11
// baseline (speedup 1.0000x reference)
#include <cuda_runtime.h>
#include <cuda_fp16.h>
#include <cstdint>

#define NN 100000
#define EMAX 1700000
#define NB 391            // ceil(NN/256)

// ---------------- scratch: static __device__ globals ----------------
__device__ float  g_dinv[NN];
__device__ int    g_cnt [NN];          // in-degree (no self-loop)
__device__ int    g_rowptr[NN];
__device__ int    g_fill[NN];
__device__ int    g_bsum[NB];
__device__ uint2  g_csr2[EMAX];        // {src, bits(dinv[src])} grouped by dst
__device__ uint2  g_hs1 [NN * 16];     // UNSCALED x@W1 as fp16 [N,64]
__device__ float4 g_h1d [NN * 16];     // relu+dropout fp32 [N,64]
__device__ uint2  g_hs2 [NN * 8];      // (h1d@W2)*dinv as fp16 [N,32]
__device__ unsigned g_oddor;           // ==0 -> edge_index int64, !=0 -> int32

// ---------------- helpers ----------------
__device__ __forceinline__ int edge_at(const void* ei, int is64, long long idx) {
    if (is64) return (int)((const long long*)ei)[idx];
    return ((const int*)ei)[idx];
}

// ---------------- JAX Threefry-2x32, key = (0, 42) ----------------
__device__ __forceinline__ void threefry_0_42(uint32_t c0, uint32_t c1,
                                              uint32_t& o0, uint32_t& o1) {
    const uint32_t ks0 = 0u;
    const uint32_t ks1 = 42u;
    const uint32_t ks2 = 0x1BD11BDAu ^ 0u ^ 42u;
    uint32_t x0 = c0 + ks0;
    uint32_t x1 = c1 + ks1;
#define TF_RND(r) { x0 += x1; x1 = (x1 << (r)) | (x1 >> (32 - (r))); x1 ^= x0; }
    TF_RND(13) TF_RND(15) TF_RND(26) TF_RND(6)
    x0 += ks1; x1 += ks2 + 1u;
    TF_RND(17) TF_RND(29) TF_RND(16) TF_RND(24)
    x0 += ks2; x1 += ks0 + 2u;
    TF_RND(13) TF_RND(15) TF_RND(26) TF_RND(6)
    x0 += ks0; x1 += ks1 + 3u;
    TF_RND(17) TF_RND(29) TF_RND(16) TF_RND(24)
    x0 += ks1; x1 += ks2 + 4u;
    TF_RND(13) TF_RND(15) TF_RND(26) TF_RND(6)
    x0 += ks2; x1 += ks0 + 5u;
#undef TF_RND
    o0 = x0; o1 = x1;
}

__device__ __forceinline__ bool jax_keep(uint32_t bits) {
    float f = __uint_as_float((bits >> 9) | 0x3f800000u) - 1.0f;
    return f < 0.8f;
}

// ---------------- reset (zero cnt) + sampled dtype detection ----------------
__global__ void reset_detect_kernel(const unsigned* w) {
    int i = blockIdx.x * blockDim.x + threadIdx.x;
    if (i < NN) g_cnt[i] = 0;
    if (blockIdx.x < 32) {
        unsigned acc = w[2 * i + 1];
        for (int o = 16; o > 0; o >>= 1) acc |= __shfl_down_sync(0xffffffffu, acc, o);
        if ((threadIdx.x & 31) == 0 && acc) atomicOr(&g_oddor, acc);
    }
}

// ---------------- degree counts ----------------
__global__ void deg_cnt_kernel(const void* ei, int E) {
    int is64 = (g_oddor == 0u);
    int e = blockIdx.x * blockDim.x + threadIdx.x;
    if (e < E) {
        int d = edge_at(ei, is64, (long long)E + e);
        if ((unsigned)d < NN) atomicAdd(&g_cnt[d], 1);
    }
}

// ---------------- scan level 1 (also computes dinv) ----------------
__global__ void scan1_kernel() {
    __shared__ int s[256];
    int i = blockIdx.x * 256 + threadIdx.x;
    int v = (i < NN) ? g_cnt[i] : 0;
    if (i < NN) g_dinv[i] = rsqrtf(1.0f + (float)v);
    s[threadIdx.x] = v;
    __syncthreads();
    for (int o = 1; o < 256; o <<= 1) {
        int t = (threadIdx.x >= o) ? s[threadIdx.x - o] : 0;
        __syncthreads();
        s[threadIdx.x] += t;
        __syncthreads();
    }
    if (i < NN) g_rowptr[i] = s[threadIdx.x] - v;
    if (threadIdx.x == 255) g_bsum[blockIdx.x] = s[255];
}

// ---------------- scan level 2+3 merged: each block reduces its bsum prefix ----------------
__global__ void scan3_kernel() {
    __shared__ int red[256];
    const int b = blockIdx.x;
    const int t = threadIdx.x;
    int sum = 0;
    for (int j = t; j < b; j += 256) sum += g_bsum[j];
    red[t] = sum;
    __syncthreads();
    for (int o = 128; o > 0; o >>= 1) {
        if (t < o) red[t] += red[t + o];
        __syncthreads();
    }
    int prefix = red[0];
    int i = b * 256 + t;
    if (i < NN) {
        int r = g_rowptr[i] + prefix;
        g_rowptr[i] = r;
        g_fill[i]   = r;
    }
}

// ---------------- CSR build: {src, dinv[src]} grouped by dst ----------------
__global__ void build_kernel(const void* ei, int E) {
    int is64 = (g_oddor == 0u);
    int e = blockIdx.x * blockDim.x + threadIdx.x;
    if (e >= E) return;
    int s = edge_at(ei, is64, e);
    int d = edge_at(ei, is64, (long long)E + e);
    if ((unsigned)s >= NN || (unsigned)d >= NN) return;
    int pos = atomicAdd(&g_fill[d], 1);
    if (pos < EMAX) {
        uint2 entry;
        entry.x = (unsigned)s;
        entry.y = __float_as_uint(__ldg(&g_dinv[s]));
        g_csr2[pos] = entry;
    }
}

// ---------------- GEMM layer 1 (independent branch): hs1 = fp16(X@W1)  K=128, C=64 ----------------
// 256 threads, 64 rows/block, 4x4 thread tile, K-chunks of 16. NO dinv dependency.
__global__ void gemm1_kernel(const float* __restrict__ X, const float* __restrict__ W) {
    __shared__ float Ws[128 * 64];          // 32 KB
    __shared__ float Xs[16 * 68];
    const int tid = threadIdx.x;
    const int n0  = blockIdx.x * 64;

    for (int i = tid; i < 128 * 64 / 4; i += 256)
        ((float4*)Ws)[i] = ((const float4*)W)[i];

    const int tc = tid & 15;
    const int tr = tid >> 4;
    const int lr = tid >> 2;
    const int lq = tid & 3;

    float a[4][4] = {};

    for (int kc = 0; kc < 128; kc += 16) {
        __syncthreads();
        {
            int n = n0 + lr;
            float4 v = make_float4(0.f, 0.f, 0.f, 0.f);
            if (n < NN) v = *(const float4*)(X + (size_t)n * 128 + kc + lq * 4);
            Xs[(lq * 4 + 0) * 68 + lr] = v.x;
            Xs[(lq * 4 + 1) * 68 + lr] = v.y;
            Xs[(lq * 4 + 2) * 68 + lr] = v.z;
            Xs[(lq * 4 + 3) * 68 + lr] = v.w;
        }
        __syncthreads();
#pragma unroll
        for (int k = 0; k < 16; ++k) {
            float4 xv = *(const float4*)(&Xs[k * 68 + tr * 4]);
            float4 wv = *(const float4*)(&Ws[(kc + k) * 64 + tc * 4]);
            float xr[4] = {xv.x, xv.y, xv.z, xv.w};
            float wr[4] = {wv.x, wv.y, wv.z, wv.w};
#pragma unroll
            for (int i = 0; i < 4; ++i)
#pragma unroll
                for (int j = 0; j < 4; ++j)
                    a[i][j] = fmaf(xr[i], wr[j], a[i][j]);
        }
    }

#pragma unroll
    for (int i = 0; i < 4; ++i) {
        int n = n0 + tr * 4 + i;
        if (n < NN) {
            __half2 h0 = __floats2half2_rn(a[i][0], a[i][1]);
            __half2 h1 = __floats2half2_rn(a[i][2], a[i][3]);
            uint2 u;
            u.x = *(unsigned*)&h0;
            u.y = *(unsigned*)&h1;
            g_hs1[(size_t)n * 16 + tc] = u;
        }
    }
}

// ---------------- aggregate layer 1: acc = dinv_n*h_n + sum dinv_s*h_s; bias/relu/dropout ----------------
__global__ void agg1_kernel(const float* __restrict__ b1) {
    int gw = (blockIdx.x * blockDim.x + threadIdx.x) >> 5;
    if (gw >= NN) return;
    const int lane = threadIdx.x & 31;
    const int n = gw;
    const __half2* hs = (const __half2*)g_hs1;

    const float di = g_dinv[n];
    float2 self = __half22float2(__ldg(&hs[(size_t)n * 32 + lane]));
    float2 acc;
    acc.x = di * self.x;
    acc.y = di * self.y;

    const int start = g_rowptr[n];
    const int cnt   = g_cnt[n];

    int i = 0;
    for (; i + 8 <= cnt; i += 8) {
        uint2 ed[8];
#pragma unroll
        for (int u = 0; u < 8; ++u) ed[u] = __ldg(&g_csr2[start + i + u]);
        float2 v[8];
#pragma unroll
        for (int u = 0; u < 8; ++u) v[u] = __half22float2(__ldg(&hs[(size_t)ed[u].x * 32 + lane]));
#pragma unroll
        for (int u = 0; u < 8; ++u) {
            float sc = __uint_as_float(ed[u].y);
            acc.x = fmaf(sc, v[u].x, acc.x);
            acc.y = fmaf(sc, v[u].y, acc.y);
        }
    }
    for (; i < cnt; ++i) {
        uint2 ed = __ldg(&g_csr2[start + i]);
        float2 v = __half22float2(__ldg(&hs[(size_t)ed.x * 32 + lane]));
        float sc = __uint_as_float(ed.y);
        acc.x = fmaf(sc, v.x, acc.x);
        acc.y = fmaf(sc, v.y, acc.y);
    }

    const int c0 = lane * 2;
    float vx = fmaxf(di * acc.x + b1[c0 + 0], 0.0f);
    float vy = fmaxf(di * acc.y + b1[c0 + 1], 0.0f);

    int j = n * 64 + c0;
    uint32_t a0, a1, b0, b1w;
    threefry_0_42(0u, (uint32_t)j,     a0, a1);
    threefry_0_42(0u, (uint32_t)(j+1), b0, b1w);
    float2 o;
    o.x = jax_keep(a0 ^ a1)  ? vx * 1.25f : 0.0f;
    o.y = jax_keep(b0 ^ b1w) ? vy * 1.25f : 0.0f;
    ((float2*)g_h1d)[(size_t)n * 32 + lane] = o;
}

// ---------------- GEMM layer 2: hs2 = fp16((h1d @ W2) * dinv)  K=64, C=32 ----------------
__global__ void gemm2_kernel(const float* __restrict__ W) {
    __shared__ float Ws[64 * 32];
    __shared__ float Xs[16 * 132];
    const int tid = threadIdx.x;
    const int n0  = blockIdx.x * 128;
    const float* X = (const float*)g_h1d;

    for (int i = tid; i < 64 * 32 / 4; i += 256)
        ((float4*)Ws)[i] = ((const float4*)W)[i];

    const int tc = tid & 7;
    const int tr = tid >> 3;
    const int lr2 = tid >> 1;
    const int lq2 = tid & 1;

    float a[4][4] = {};

    for (int kc = 0; kc < 64; kc += 16) {
        __syncthreads();
        {
#pragma unroll
            for (int h = 0; h < 2; ++h) {
                int r = lr2;
                int q = lq2 * 2 + h;
                int n = n0 + r;
                float4 v = make_float4(0.f, 0.f, 0.f, 0.f);
                if (n < NN) v = *(const float4*)(X + (size_t)n * 64 + kc + q * 4);
                Xs[(q * 4 + 0) * 132 + r] = v.x;
                Xs[(q * 4 + 1) * 132 + r] = v.y;
                Xs[(q * 4 + 2) * 132 + r] = v.z;
                Xs[(q * 4 + 3) * 132 + r] = v.w;
            }
        }
        __syncthreads();
#pragma unroll
        for (int k = 0; k < 16; ++k) {
            float4 xv = *(const float4*)(&Xs[k * 132 + tr * 4]);
            float4 wv = *(const float4*)(&Ws[(kc + k) * 32 + tc * 4]);
            float xr[4] = {xv.x, xv.y, xv.z, xv.w};
            float wr[4] = {wv.x, wv.y, wv.z, wv.w};
#pragma unroll
            for (int i = 0; i < 4; ++i)
#pragma unroll
                for (int j = 0; j < 4; ++j)
                    a[i][j] = fmaf(xr[i], wr[j], a[i][j]);
        }
    }

#pragma unroll
    for (int i = 0; i < 4; ++i) {
        int n = n0 + tr * 4 + i;
        if (n < NN) {
            float s = g_dinv[n];
            __half2 h0 = __floats2half2_rn(a[i][0] * s, a[i][1] * s);
            __half2 h1 = __floats2half2_rn(a[i][2] * s, a[i][3] * s);
            uint2 u;
            u.x = *(unsigned*)&h0;
            u.y = *(unsigned*)&h1;
            g_hs2[(size_t)n * 8 + tc] = u;   // cols tc*4..tc*4+3
        }
    }
}

// ---------------- aggregate layer 2 (fp16 gather) + bias ----------------
__global__ void agg2_kernel(const float* __restrict__ b2, float* __restrict__ out) {
    int gw = (blockIdx.x * blockDim.x + threadIdx.x) >> 5;
    if (gw >= NN) return;
    const int lane = threadIdx.x & 31;
    const int n = gw;
    const __half* hs = (const __half*)g_hs2;

    float acc = __half2float(__ldg(&hs[(size_t)n * 32 + lane]));   // self (pre-scaled)
    const int start = g_rowptr[n];
    const int cnt   = g_cnt[n];

    int i = 0;
    for (; i + 8 <= cnt; i += 8) {
        uint2 ed[8];
#pragma unroll
        for (int u = 0; u < 8; ++u) ed[u] = __ldg(&g_csr2[start + i + u]);
        float v[8];
#pragma unroll
        for (int u = 0; u < 8; ++u) v[u] = __half2float(__ldg(&hs[(size_t)ed[u].x * 32 + lane]));
        acc += ((v[0] + v[1]) + (v[2] + v[3])) + ((v[4] + v[5]) + (v[6] + v[7]));
    }
    for (; i < cnt; ++i) {
        uint2 ed = __ldg(&g_csr2[start + i]);
        acc += __half2float(__ldg(&hs[(size_t)ed.x * 32 + lane]));
    }

    out[(size_t)n * 32 + lane] = g_dinv[n] * acc + b2[lane];
}

// ---------------- launch: forked graph ----------------
extern "C" void kernel_launch(void* const* d_in, const int* in_sizes, int n_in,
                              void* d_out, int out_size) {
    const float* x  = (const float*)d_in[0];
    const void*  ei = d_in[1];
    const float* W1 = (const float*)d_in[2];
    const float* b1 = (const float*)d_in[3];
    const float* W2 = (const float*)d_in[4];
    const float* b2 = (const float*)d_in[5];
    float*       out = (float*)d_out;

    const int N = NN;
    const int E = in_sizes[1] / 2;

    // created once on the first (uncaptured, correctness) call
    static cudaStream_t s1 = nullptr;
    static cudaEvent_t  e0 = nullptr, e1 = nullptr;
    if (!s1) {
        cudaStreamCreateWithFlags(&s1, cudaStreamNonBlocking);
        cudaEventCreateWithFlags(&e0, cudaEventDisableTiming);
        cudaEventCreateWithFlags(&e1, cudaEventDisableTiming);
    }

    // ---- fork: gemm1 (independent of edges) on s1 ----
    cudaEventRecord(e0, 0);
    cudaStreamWaitEvent(s1, e0, 0);
    gemm1_kernel<<<(N + 63) / 64, 256, 0, s1>>>(x, W1);
    cudaEventRecord(e1, s1);

    // ---- main branch: preprocessing ----
    reset_detect_kernel<<<NB, 256>>>((const unsigned*)ei);
    deg_cnt_kernel<<<(E + 255) / 256, 256>>>(ei, E);
    scan1_kernel<<<NB, 256>>>();
    scan3_kernel<<<NB, 256>>>();
    build_kernel<<<(E + 255) / 256, 256>>>(ei, E);

    // ---- join, then the serial tail ----
    cudaStreamWaitEvent(0, e1, 0);
    agg1_kernel<<<(N * 32 + 255) / 256, 256>>>(b1);
    gemm2_kernel<<<(N + 127) / 128, 256>>>(W2);
    agg2_kernel<<<(N * 32 + 255) / 256, 256>>>(b2, out);
}

// round 13
// speedup vs baseline: 1.5091x; 1.5091x over previous
#include <cuda_runtime.h>
#include <cuda_fp16.h>
#include <cstdint>

#define NN 100000
#define EMAX 1700000
#define NB 391            // ceil(NN/256)

// ---------------- scratch: static __device__ globals ----------------
__device__ float  g_dinv[NN];
__device__ int    g_cnt [NN];          // in-degree (no self-loop)
__device__ int    g_rowptr[NN];
__device__ int    g_fill[NN];
__device__ int    g_bsum[NB];
__device__ int    g_csr [EMAX];        // src indices grouped by dst
__device__ uint2  g_hs1 [NN * 16];     // (x@W1)*dinv as fp16 [N,64]
__device__ float4 g_h1d [NN * 16];     // relu+dropout fp32 [N,64]
__device__ uint2  g_hs2 [NN * 8];      // (h1d@W2)*dinv as fp16 [N,32]
__device__ unsigned g_oddor;           // ==0 -> edge_index int64, !=0 -> int32

// ---------------- helpers ----------------
__device__ __forceinline__ int edge_at(const void* ei, int is64, long long idx) {
    if (is64) return (int)((const long long*)ei)[idx];
    return ((const int*)ei)[idx];
}

// ---------------- JAX Threefry-2x32, key = (0, 42) ----------------
__device__ __forceinline__ void threefry_0_42(uint32_t c0, uint32_t c1,
                                              uint32_t& o0, uint32_t& o1) {
    const uint32_t ks0 = 0u;
    const uint32_t ks1 = 42u;
    const uint32_t ks2 = 0x1BD11BDAu ^ 0u ^ 42u;
    uint32_t x0 = c0 + ks0;
    uint32_t x1 = c1 + ks1;
#define TF_RND(r) { x0 += x1; x1 = (x1 << (r)) | (x1 >> (32 - (r))); x1 ^= x0; }
    TF_RND(13) TF_RND(15) TF_RND(26) TF_RND(6)
    x0 += ks1; x1 += ks2 + 1u;
    TF_RND(17) TF_RND(29) TF_RND(16) TF_RND(24)
    x0 += ks2; x1 += ks0 + 2u;
    TF_RND(13) TF_RND(15) TF_RND(26) TF_RND(6)
    x0 += ks0; x1 += ks1 + 3u;
    TF_RND(17) TF_RND(29) TF_RND(16) TF_RND(24)
    x0 += ks1; x1 += ks2 + 4u;
    TF_RND(13) TF_RND(15) TF_RND(26) TF_RND(6)
    x0 += ks2; x1 += ks0 + 5u;
#undef TF_RND
    o0 = x0; o1 = x1;
}

__device__ __forceinline__ bool jax_keep(uint32_t bits) {
    float f = __uint_as_float((bits >> 9) | 0x3f800000u) - 1.0f;
    return f < 0.8f;
}

// ---------------- reset (zero cnt) + sampled dtype detection ----------------
__global__ void reset_detect_kernel(const unsigned* w) {
    int i = blockIdx.x * blockDim.x + threadIdx.x;
    if (i < NN) g_cnt[i] = 0;
    if (blockIdx.x < 32) {
        unsigned acc = w[2 * i + 1];
        for (int o = 16; o > 0; o >>= 1) acc |= __shfl_down_sync(0xffffffffu, acc, o);
        if ((threadIdx.x & 31) == 0 && acc) atomicOr(&g_oddor, acc);
    }
}

// ---------------- degree counts ----------------
__global__ void deg_cnt_kernel(const void* ei, int E) {
    int is64 = (g_oddor == 0u);
    int e = blockIdx.x * blockDim.x + threadIdx.x;
    if (e < E) {
        int d = edge_at(ei, is64, (long long)E + e);
        if ((unsigned)d < NN) atomicAdd(&g_cnt[d], 1);
    }
}

// ---------------- scan level 1 (also computes dinv) ----------------
__global__ void scan1_kernel() {
    __shared__ int s[256];
    int i = blockIdx.x * 256 + threadIdx.x;
    int v = (i < NN) ? g_cnt[i] : 0;
    if (i < NN) g_dinv[i] = rsqrtf(1.0f + (float)v);
    s[threadIdx.x] = v;
    __syncthreads();
    for (int o = 1; o < 256; o <<= 1) {
        int t = (threadIdx.x >= o) ? s[threadIdx.x - o] : 0;
        __syncthreads();
        s[threadIdx.x] += t;
        __syncthreads();
    }
    if (i < NN) g_rowptr[i] = s[threadIdx.x] - v;
    if (threadIdx.x == 255) g_bsum[blockIdx.x] = s[255];
}

// ---------------- scan level 2+3 merged: each block reduces its bsum prefix ----------------
__global__ void scan3_kernel() {
    __shared__ int red[256];
    const int b = blockIdx.x;
    const int t = threadIdx.x;
    int sum = 0;
    for (int j = t; j < b; j += 256) sum += g_bsum[j];
    red[t] = sum;
    __syncthreads();
    for (int o = 128; o > 0; o >>= 1) {
        if (t < o) red[t] += red[t + o];
        __syncthreads();
    }
    int prefix = red[0];
    int i = b * 256 + t;
    if (i < NN) {
        int r = g_rowptr[i] + prefix;
        g_rowptr[i] = r;
        g_fill[i]   = r;
    }
}

// ---------------- CSR build ----------------
__global__ void build_kernel(const void* ei, int E) {
    int is64 = (g_oddor == 0u);
    int e = blockIdx.x * blockDim.x + threadIdx.x;
    if (e >= E) return;
    int s = edge_at(ei, is64, e);
    int d = edge_at(ei, is64, (long long)E + e);
    if ((unsigned)s >= NN || (unsigned)d >= NN) return;
    int pos = atomicAdd(&g_fill[d], 1);
    if (pos < EMAX) g_csr[pos] = s;
}

// ---------------- GEMM layer 1: hs1 = fp16((X@W1)*dinv)  K=128, C=64 ----------------
// 256 threads, 64 rows/block, 4x4 thread tile, K-chunks of 16.
__global__ void gemm1_kernel(const float* __restrict__ X, const float* __restrict__ W) {
    __shared__ float Ws[128 * 64];          // 32 KB (full W)
    __shared__ float Xs[16 * 68];           // K-chunk of X, transposed, pad 68
    const int tid = threadIdx.x;
    const int n0  = blockIdx.x * 64;

    for (int i = tid; i < 128 * 64 / 4; i += 256)
        ((float4*)Ws)[i] = ((const float4*)W)[i];

    const int tc = tid & 15;                // col group 0..15
    const int tr = tid >> 4;                // row group 0..15
    const int lr = tid >> 2;                // load row 0..63
    const int lq = tid & 3;                 // load quad 0..3

    float a[4][4] = {};

    for (int kc = 0; kc < 128; kc += 16) {
        __syncthreads();
        {
            int n = n0 + lr;
            float4 v = make_float4(0.f, 0.f, 0.f, 0.f);
            if (n < NN) v = *(const float4*)(X + (size_t)n * 128 + kc + lq * 4);
            Xs[(lq * 4 + 0) * 68 + lr] = v.x;
            Xs[(lq * 4 + 1) * 68 + lr] = v.y;
            Xs[(lq * 4 + 2) * 68 + lr] = v.z;
            Xs[(lq * 4 + 3) * 68 + lr] = v.w;
        }
        __syncthreads();
#pragma unroll
        for (int k = 0; k < 16; ++k) {
            float4 xv = *(const float4*)(&Xs[k * 68 + tr * 4]);
            float4 wv = *(const float4*)(&Ws[(kc + k) * 64 + tc * 4]);
            float xr[4] = {xv.x, xv.y, xv.z, xv.w};
            float wr[4] = {wv.x, wv.y, wv.z, wv.w};
#pragma unroll
            for (int i = 0; i < 4; ++i)
#pragma unroll
                for (int j = 0; j < 4; ++j)
                    a[i][j] = fmaf(xr[i], wr[j], a[i][j]);
        }
    }

#pragma unroll
    for (int i = 0; i < 4; ++i) {
        int n = n0 + tr * 4 + i;
        if (n < NN) {
            float s = g_dinv[n];
            __half2 h0 = __floats2half2_rn(a[i][0] * s, a[i][1] * s);
            __half2 h1 = __floats2half2_rn(a[i][2] * s, a[i][3] * s);
            uint2 u;
            u.x = *(unsigned*)&h0;
            u.y = *(unsigned*)&h1;
            g_hs1[(size_t)n * 16 + tc] = u;   // cols tc*4..tc*4+3
        }
    }
}

// ---------------- aggregate layer 1 (fp16 gather) + bias/relu/dropout ----------------
__global__ void agg1_kernel(const float* __restrict__ b1) {
    int gw = (blockIdx.x * blockDim.x + threadIdx.x) >> 5;
    if (gw >= NN) return;
    const int lane = threadIdx.x & 31;
    const int n = gw;
    const __half2* hs = (const __half2*)g_hs1;

    float2 acc = __half22float2(__ldg(&hs[(size_t)n * 32 + lane]));   // self-loop
    const int start = g_rowptr[n];
    const int cnt   = g_cnt[n];

    int i = 0;
    for (; i + 8 <= cnt; i += 8) {
        int s[8];
#pragma unroll
        for (int u = 0; u < 8; ++u) s[u] = __ldg(&g_csr[start + i + u]);
        float2 v[8];
#pragma unroll
        for (int u = 0; u < 8; ++u) v[u] = __half22float2(__ldg(&hs[(size_t)s[u] * 32 + lane]));
        float sx = ((v[0].x + v[1].x) + (v[2].x + v[3].x)) +
                   ((v[4].x + v[5].x) + (v[6].x + v[7].x));
        float sy = ((v[0].y + v[1].y) + (v[2].y + v[3].y)) +
                   ((v[4].y + v[5].y) + (v[6].y + v[7].y));
        acc.x += sx; acc.y += sy;
    }
    for (; i < cnt; ++i) {
        int s = __ldg(&g_csr[start + i]);
        float2 v = __half22float2(__ldg(&hs[(size_t)s * 32 + lane]));
        acc.x += v.x; acc.y += v.y;
    }

    const float di = g_dinv[n];
    const int c0 = lane * 2;
    float vx = fmaxf(di * acc.x + b1[c0 + 0], 0.0f);
    float vy = fmaxf(di * acc.y + b1[c0 + 1], 0.0f);

    int j = n * 64 + c0;
    uint32_t a0, a1, b0, b1w;
    threefry_0_42(0u, (uint32_t)j,     a0, a1);
    threefry_0_42(0u, (uint32_t)(j+1), b0, b1w);
    float2 o;
    o.x = jax_keep(a0 ^ a1)  ? vx * 1.25f : 0.0f;
    o.y = jax_keep(b0 ^ b1w) ? vy * 1.25f : 0.0f;
    ((float2*)g_h1d)[(size_t)n * 32 + lane] = o;
}

// ---------------- GEMM layer 2: hs2 = fp16((h1d @ W2) * dinv)  K=64, C=32 ----------------
// 256 threads, 128 rows/block, 4x4 thread tile, K-chunks of 16.
__global__ void gemm2_kernel(const float* __restrict__ W) {
    __shared__ float Ws[64 * 32];           // 8 KB
    __shared__ float Xs[16 * 132];          // K-chunk of h1d, transposed
    const int tid = threadIdx.x;
    const int n0  = blockIdx.x * 128;
    const float* X = (const float*)g_h1d;

    for (int i = tid; i < 64 * 32 / 4; i += 256)
        ((float4*)Ws)[i] = ((const float4*)W)[i];

    const int tc = tid & 7;                 // col group 0..7
    const int tr = tid >> 3;                // row group 0..31
    const int lr2 = tid >> 1;               // load row
    const int lq2 = tid & 1;

    float a[4][4] = {};

    for (int kc = 0; kc < 64; kc += 16) {
        __syncthreads();
        {
#pragma unroll
            for (int h = 0; h < 2; ++h) {
                int r = lr2;
                int q = lq2 * 2 + h;
                int n = n0 + r;
                float4 v = make_float4(0.f, 0.f, 0.f, 0.f);
                if (n < NN) v = *(const float4*)(X + (size_t)n * 64 + kc + q * 4);
                Xs[(q * 4 + 0) * 132 + r] = v.x;
                Xs[(q * 4 + 1) * 132 + r] = v.y;
                Xs[(q * 4 + 2) * 132 + r] = v.z;
                Xs[(q * 4 + 3) * 132 + r] = v.w;
            }
        }
        __syncthreads();
#pragma unroll
        for (int k = 0; k < 16; ++k) {
            float4 xv = *(const float4*)(&Xs[k * 132 + tr * 4]);
            float4 wv = *(const float4*)(&Ws[(kc + k) * 32 + tc * 4]);
            float xr[4] = {xv.x, xv.y, xv.z, xv.w};
            float wr[4] = {wv.x, wv.y, wv.z, wv.w};
#pragma unroll
            for (int i = 0; i < 4; ++i)
#pragma unroll
                for (int j = 0; j < 4; ++j)
                    a[i][j] = fmaf(xr[i], wr[j], a[i][j]);
        }
    }

#pragma unroll
    for (int i = 0; i < 4; ++i) {
        int n = n0 + tr * 4 + i;
        if (n < NN) {
            float s = g_dinv[n];
            __half2 h0 = __floats2half2_rn(a[i][0] * s, a[i][1] * s);
            __half2 h1 = __floats2half2_rn(a[i][2] * s, a[i][3] * s);
            uint2 u;
            u.x = *(unsigned*)&h0;
            u.y = *(unsigned*)&h1;
            g_hs2[(size_t)n * 8 + tc] = u;   // cols tc*4..tc*4+3
        }
    }
}

// ---------------- aggregate layer 2 (fp16 gather) + bias ----------------
__global__ void agg2_kernel(const float* __restrict__ b2, float* __restrict__ out) {
    int gw = (blockIdx.x * blockDim.x + threadIdx.x) >> 5;
    if (gw >= NN) return;
    const int lane = threadIdx.x & 31;
    const int n = gw;
    const __half* hs = (const __half*)g_hs2;

    float acc = __half2float(__ldg(&hs[(size_t)n * 32 + lane]));   // self (pre-scaled)
    const int start = g_rowptr[n];
    const int cnt   = g_cnt[n];

    int i = 0;
    for (; i + 8 <= cnt; i += 8) {
        int s[8];
#pragma unroll
        for (int u = 0; u < 8; ++u) s[u] = __ldg(&g_csr[start + i + u]);
        float v[8];
#pragma unroll
        for (int u = 0; u < 8; ++u) v[u] = __half2float(__ldg(&hs[(size_t)s[u] * 32 + lane]));
        acc += ((v[0] + v[1]) + (v[2] + v[3])) + ((v[4] + v[5]) + (v[6] + v[7]));
    }
    for (; i < cnt; ++i) {
        int s = __ldg(&g_csr[start + i]);
        acc += __half2float(__ldg(&hs[(size_t)s * 32 + lane]));
    }

    out[(size_t)n * 32 + lane] = g_dinv[n] * acc + b2[lane];
}

// ---------------- launch: single stream ----------------
extern "C" void kernel_launch(void* const* d_in, const int* in_sizes, int n_in,
                              void* d_out, int out_size) {
    const float* x  = (const float*)d_in[0];
    const void*  ei = d_in[1];
    const float* W1 = (const float*)d_in[2];
    const float* b1 = (const float*)d_in[3];
    const float* W2 = (const float*)d_in[4];
    const float* b2 = (const float*)d_in[5];
    float*       out = (float*)d_out;

    const int N = NN;
    const int E = in_sizes[1] / 2;

    reset_detect_kernel<<<NB, 256>>>((const unsigned*)ei);
    deg_cnt_kernel<<<(E + 255) / 256, 256>>>(ei, E);

    scan1_kernel<<<NB, 256>>>();
    scan3_kernel<<<NB, 256>>>();
    build_kernel<<<(E + 255) / 256, 256>>>(ei, E);

    gemm1_kernel<<<(N + 63) / 64, 256>>>(x, W1);
    agg1_kernel<<<(N * 32 + 255) / 256, 256>>>(b1);

    gemm2_kernel<<<(N + 127) / 128, 256>>>(W2);
    agg2_kernel<<<(N * 32 + 255) / 256, 256>>>(b2, out);
}